// round 15
// baseline (speedup 1.0000x reference)
#include <cuda_runtime.h>
#include <cuda_fp16.h>

#define C_DIM 2048
#define B_DIM 64
#define I_DIM 8
#define U_DIM 32
#define D_DIM 16
#define UD    512
#define NBLK  148
#define NTH   1024

typedef unsigned long long u64;
typedef unsigned int u32;

// ---- scratch (static __device__: allocation-free) ----
__device__ float g_xt[C_DIM * B_DIM * I_DIM];       // x transposed: [c][b][i]
__device__ float g_spart[NBLK * B_DIM * UD];        // per-block s partials
__device__ u32   g_vh[(B_DIM / 2) * UD];            // v half2 pairs: [b/2][ud]
__device__ float g_b[C_DIM * U_DIM];                // routing logits
__device__ u32   g_uh[C_DIM * (B_DIM / 2) * UD];    // u_hat half2: [c][b/2][ud] (128 MB)

__device__ __forceinline__ u64 mul2(u64 a, u64 b) {
    u64 r; asm("mul.rn.f32x2 %0, %1, %2;" : "=l"(r) : "l"(a), "l"(b)); return r;
}
__device__ __forceinline__ u64 fma2(u64 a, u64 b, u64 c) {
    u64 r; asm("fma.rn.f32x2 %0, %1, %2, %3;" : "=l"(r) : "l"(a), "l"(b), "l"(c)); return r;
}
__device__ __forceinline__ float hadd2(u64 a) {
    float lo, hi; asm("mov.b64 {%0,%1}, %2;" : "=f"(lo), "=f"(hi) : "l"(a));
    return lo + hi;
}
__device__ __forceinline__ u32 ldg_u32(const u32* p) {
    u32 r; asm volatile("ld.global.nc.b32 %0, [%1];" : "=r"(r) : "l"(p)); return r;
}
__device__ __forceinline__ u32 smem_u32(const void* p) {
    return (u32)__cvta_generic_to_shared(p);
}
__device__ __forceinline__ void lds_2u64(u32 a, u64& x, u64& y) {
    asm("ld.shared.v2.u64 {%0,%1}, [%2];" : "=l"(x), "=l"(y) : "r"(a));
}
__device__ __forceinline__ void lds_2u64v(u32 a, u64& x, u64& y) {
    asm volatile("ld.shared.v2.u64 {%0,%1}, [%2];" : "=l"(x), "=l"(y) : "r"(a));
}
__device__ __forceinline__ u32 lds_u32(u32 a) {
    u32 r; asm volatile("ld.shared.b32 %0, [%1];" : "=r"(r) : "r"(a)); return r;
}
__device__ __forceinline__ float dot8(u64 wa0, u64 wa1, u64 wb0, u64 wb1,
                                      u64 x0, u64 x1, u64 x2, u64 x3) {
    u64 acc = mul2(wa0, x0);
    acc = fma2(wa1, x1, acc);
    acc = fma2(wb0, x2, acc);
    acc = fma2(wb1, x3, acc);
    return hadd2(acc);
}

// ---- mbarrier + bulk-copy helpers ----
__device__ __forceinline__ void mbar_init(u32 a, u32 cnt) {
    asm volatile("mbarrier.init.shared.b64 [%0], %1;" :: "r"(a), "r"(cnt) : "memory");
}
__device__ __forceinline__ void fence_async() {
    asm volatile("fence.proxy.async.shared::cta;" ::: "memory");
}
__device__ __forceinline__ void mbar_expect(u32 a, u32 bytes) {
    asm volatile("mbarrier.arrive.expect_tx.shared.b64 _, [%0], %1;"
                 :: "r"(a), "r"(bytes) : "memory");
}
__device__ __forceinline__ void mbar_arrive(u32 a) {
    asm volatile("mbarrier.arrive.shared.b64 _, [%0];" :: "r"(a) : "memory");
}
__device__ __forceinline__ void bulk_g2s(u32 dst, const void* src, u32 bytes, u32 mbar) {
    asm volatile("cp.async.bulk.shared::cta.global.mbarrier::complete_tx::bytes "
                 "[%0], [%1], %2, [%3];"
                 :: "r"(dst), "l"(src), "r"(bytes), "r"(mbar) : "memory");
}
__device__ __forceinline__ void mbar_wait(u32 a, u32 parity) {
    asm volatile(
        "{\n\t.reg .pred P;\n"
        "W_%=:\n\t"
        "mbarrier.try_wait.parity.shared.b64 P, [%0], %1;\n\t"
        "@!P bra W_%=;\n\t"
        "}" :: "r"(a), "r"(parity) : "memory");
}

// x (B,I,C) -> g_xt[c][b][i]
__global__ void k_transpose(const float* __restrict__ x) {
    int idx = blockIdx.x * blockDim.x + threadIdx.x;
    if (idx >= C_DIM * B_DIM * I_DIM) return;
    int c = idx >> 9;
    int r = idx & 511;
    int b = r >> 3;
    int i = r & 7;
    g_xt[idx] = x[(b * I_DIM + i) * C_DIM + c];
}

// ---------------------------------------------------------------------------
// p0: einsum -> u_hat (fp16, gmem) + s1 partials (uniform cij = 1/32).
// Ring-3 staged W/x via cp.async.bulk; NO block-wide syncs — producer/consumer
// mbarriers only, warps drift up to 2 c apart.
// ---------------------------------------------------------------------------
__global__ void __launch_bounds__(NTH, 1) k_einsum(const float* __restrict__ W) {
    extern __shared__ char dyn[];
    const u32 wbase = smem_u32(dyn);            // 3 stages x (W 16KB @ s*16384)
    const u32 xbase = wbase + 3 * 16384;        // 3 stages x (x 2KB  @ s*2048)
    __shared__ u64 full_s[3], cons_s[3];
    const u32 fb = smem_u32(full_s);
    const u32 cb = smem_u32(cons_s);

    const int tid  = threadIdx.x;
    const int w    = tid >> 5;
    const int lane = tid & 31;
    const int wu   = w & 15;
    const int wb   = w >> 4;
    const int ud   = wu * 32 + lane;

    float sacc[32];
#pragma unroll
    for (int r = 0; r < 32; r++) sacc[r] = 0.f;

    const int cbeg = (blockIdx.x * C_DIM) / NBLK;
    const int cend = ((blockIdx.x + 1) * C_DIM) / NBLK;
    const int n    = cend - cbeg;

    if (tid == 0) {
#pragma unroll
        for (int s = 0; s < 3; s++) { mbar_init(fb + s * 8, 1); mbar_init(cb + s * 8, NTH); }
        fence_async();
    }
    __syncthreads();
    if (tid == 0) {                  // prologue: stage c0, c1
#pragma unroll
        for (int j = 0; j < 2; j++) {
            mbar_expect(fb + j * 8, 18432);
            bulk_g2s(wbase + j * 16384, W + (size_t)(cbeg + j) * 4096, 16384, fb + j * 8);
            bulk_g2s(xbase + j * 2048, g_xt + (cbeg + j) * 512, 2048, fb + j * 8);
        }
    }

    int s = 0, fph = 0;
    for (int idx = 0; idx < n; idx++) {
        const int c = cbeg + idx;
        mbar_wait(fb + s * 8, fph);                 // stage s holds c

        u64 wa0, wa1, wbb0, wbb1;
        lds_2u64(wbase + s * 16384 + ud * 32, wa0, wa1);
        lds_2u64(wbase + s * 16384 + ud * 32 + 16, wbb0, wbb1);

        const u32 xb = xbase + s * 2048 + wb * 1024;
        u32* uout = g_uh + (size_t)c * 16384 + (wb * 16) * 512 + ud;

#pragma unroll
        for (int t = 0; t < 16; t++) {
            u64 x0, x1, x2, x3, y0, y1, y2, y3;
            lds_2u64v(xb + t * 64,      x0, x1);
            lds_2u64v(xb + t * 64 + 16, x2, x3);
            lds_2u64v(xb + t * 64 + 32, y0, y1);
            lds_2u64v(xb + t * 64 + 48, y2, y3);
            float ua = dot8(wa0, wa1, wbb0, wbb1, x0, x1, x2, x3);
            float ub = dot8(wa0, wa1, wbb0, wbb1, y0, y1, y2, y3);
            sacc[2 * t]     += ua;
            sacc[2 * t + 1] += ub;
            __half2 h2 = __floats2half2_rn(ua, ub);
            uout[t * 512] = *(u32*)&h2;
        }

        mbar_arrive(cb + s * 8);                    // done reading stage s

        if (tid == 0 && idx + 2 < n) {              // stage c+2 into s2
            const int s2 = (s + 2 >= 3) ? s - 1 : s + 2;
            const int K  = (idx + 2) / 3;           // prior consumptions of s2
            if (K >= 1) mbar_wait(cb + s2 * 8, (K - 1) & 1);
            mbar_expect(fb + s2 * 8, 18432);
            bulk_g2s(wbase + s2 * 16384, W + (size_t)(c + 2) * 4096, 16384, fb + s2 * 8);
            bulk_g2s(xbase + s2 * 2048, g_xt + (c + 2) * 512, 2048, fb + s2 * 8);
        }
        if (++s == 3) { s = 0; fph ^= 1; }
    }

    float* sp = g_spart + (size_t)blockIdx.x * (B_DIM * UD) + ud;
#pragma unroll
    for (int r = 0; r < 32; r++)
        sp[(wb * 32 + r) * UD] = sacc[r] * (1.0f / 32.0f);
}

// ---------------------------------------------------------------------------
// p1/p2: routing pass streaming u_hat. Ring-3 x 64KB tiles; u_hat values held
// in registers between phase A (dp) and phase B (s += cij*u).
// ---------------------------------------------------------------------------
template <int PASS>
__global__ void __launch_bounds__(NTH, 1) k_route() {
    extern __shared__ char dyn[];
    const u32 ubase = smem_u32(dyn);                // 3 x 65536
    __shared__ float red_sm[2][32];
    __shared__ u64 full_s[3], cons_s[3];
    const u32 fb = smem_u32(full_s);
    const u32 cb = smem_u32(cons_s);

    const int tid  = threadIdx.x;
    const int w    = tid >> 5;
    const int lane = tid & 31;
    const int wu   = w & 15;
    const int wb   = w >> 4;
    const int hw   = lane >> 4;
    const int ud   = wu * 32 + lane;

    float sacc[32];
#pragma unroll
    for (int r = 0; r < 32; r++) sacc[r] = 0.f;

    const int cbeg = (blockIdx.x * C_DIM) / NBLK;
    const int cend = ((blockIdx.x + 1) * C_DIM) / NBLK;
    const int n    = cend - cbeg;

    if (tid == 0) {
#pragma unroll
        for (int s = 0; s < 3; s++) { mbar_init(fb + s * 8, 1); mbar_init(cb + s * 8, NTH); }
        fence_async();
    }
    __syncthreads();
    if (tid == 0) {
#pragma unroll
        for (int j = 0; j < 2; j++) {
            mbar_expect(fb + j * 8, 65536);
            bulk_g2s(ubase + j * 65536, g_uh + (size_t)(cbeg + j) * 16384, 65536, fb + j * 8);
        }
    }

    int s = 0, fph = 0;
    for (int idx = 0; idx < n; idx++) {
        const int c = cbeg + idx;
        mbar_wait(fb + s * 8, fph);                 // tile for c landed

        float bprev = (PASS == 2) ? g_b[c * U_DIM + lane] : 0.f;
        const u32 ub0 = ubase + s * 65536 + ((wb * 16) * 512 + ud) * 4;
        const u32* vb = g_vh + (wb * 16) * 512 + ud;
        float dp = 0.f;
        u32 pk[16];                                 // u_hat held in regs

#pragma unroll
        for (int t = 0; t < 16; t++) {
            pk[t] = lds_u32(ub0 + t * 2048);
            u32 vh = ldg_u32(vb + t * 512);
            float2 uu = __half22float2(*(__half2*)&pk[t]);
            float2 vv = __half22float2(*(__half2*)&vh);
            dp = fmaf(uu.x, vv.x, dp);
            dp = fmaf(uu.y, vv.y, dp);
        }
        mbar_arrive(cb + s * 8);                    // tile reads done (regs hold data)

        // reduce dp over d (16-lane segments)
#pragma unroll
        for (int off = 8; off; off >>= 1)
            dp += __shfl_down_sync(0xffffffffu, dp, off, 16);
        if ((lane & 15) == 0)
            red_sm[wb][wu * 2 + hw] = dp;
        __syncthreads();                            // red_sm ready

        // redundant per-warp softmax over u (lane = u)
        float dv = red_sm[0][lane] + red_sm[1][lane];
        float bv = dv * (1.0f / 64.0f) + bprev;
        if (PASS == 1 && w == 0) g_b[c * U_DIM + lane] = bv;
        float m = bv;
#pragma unroll
        for (int off = 16; off; off >>= 1)
            m = fmaxf(m, __shfl_xor_sync(0xffffffffu, m, off));
        float e = __expf(bv - m);
        float ssum = e;
#pragma unroll
        for (int off = 16; off; off >>= 1)
            ssum += __shfl_xor_sync(0xffffffffu, ssum, off);
        float cij = __shfl_sync(0xffffffffu, e / ssum, wu * 2 + hw);

        if (tid == 0 && idx + 2 < n) {              // stage c+2 (post-sync: cons drained)
            const int s2 = (s + 2 >= 3) ? s - 1 : s + 2;
            const int K  = (idx + 2) / 3;
            if (K >= 1) mbar_wait(cb + s2 * 8, (K - 1) & 1);
            mbar_expect(fb + s2 * 8, 65536);
            bulk_g2s(ubase + s2 * 65536, g_uh + (size_t)(c + 2) * 16384, 65536, fb + s2 * 8);
        }

        // phase B: s += cij * u_hat (from registers)
#pragma unroll
        for (int t = 0; t < 16; t++) {
            float2 uu = __half22float2(*(__half2*)&pk[t]);
            sacc[2 * t]     = fmaf(cij, uu.x, sacc[2 * t]);
            sacc[2 * t + 1] = fmaf(cij, uu.y, sacc[2 * t + 1]);
        }
        if (++s == 3) { s = 0; fph ^= 1; }
    }

    float* sp = g_spart + (size_t)blockIdx.x * (B_DIM * UD) + ud;
#pragma unroll
    for (int r = 0; r < 32; r++)
        sp[(wb * 32 + r) * UD] = sacc[r];
}

// Reduce per-block s partials (float4, 8-way p-split), apply squash
// (mag over U axis — reference quirk). 1024 threads.
__global__ void k_redsquash(float* __restrict__ dout, int final_out) {
    __shared__ float4 part[8][128];
    __shared__ float sq[UD];
    __shared__ float rs[D_DIM];
    const int b   = blockIdx.x;
    const int tid = threadIdx.x;
    const int ph  = tid >> 7;
    const int j   = tid & 127;

    const float4* sp = ((const float4*)g_spart) + b * 128 + j;
    float4 a = make_float4(0.f, 0.f, 0.f, 0.f);
    for (int p = ph; p < NBLK; p += 8) {
        float4 t = sp[p * 8192];
        a.x += t.x; a.y += t.y; a.z += t.z; a.w += t.w;
    }
    part[ph][j] = a;
    __syncthreads();

    float4 s4 = make_float4(0.f, 0.f, 0.f, 0.f);
    if (ph == 0) {
#pragma unroll
        for (int q = 0; q < 8; q++) {
            float4 t = part[q][j];
            s4.x += t.x; s4.y += t.y; s4.z += t.z; s4.w += t.w;
        }
        sq[4 * j]     = s4.x * s4.x;
        sq[4 * j + 1] = s4.y * s4.y;
        sq[4 * j + 2] = s4.z * s4.z;
        sq[4 * j + 3] = s4.w * s4.w;
    }
    __syncthreads();
    if (tid < D_DIM) {
        float msq = 0.f;
#pragma unroll
        for (int u = 0; u < U_DIM; u++) msq += sq[u * D_DIM + tid];
        rs[tid] = sqrtf(msq) / (1.0f + msq);   // mag_sq/((1+mag_sq)*mag)
    }
    __syncthreads();
    if (ph == 0) {
        const int ud = 4 * j;
        float o0 = s4.x * rs[ud & 15];
        float o1 = s4.y * rs[(ud + 1) & 15];
        float o2 = s4.z * rs[(ud + 2) & 15];
        float o3 = s4.w * rs[(ud + 3) & 15];
        if (final_out) {
            ((float4*)dout)[b * 128 + j] = make_float4(o0, o1, o2, o3);
        } else {
            __half* vh = (__half*)g_vh;
            const int base = (b >> 1) * (UD * 2) + ud * 2 + (b & 1);
            vh[base]     = __float2half_rn(o0);
            vh[base + 2] = __float2half_rn(o1);
            vh[base + 4] = __float2half_rn(o2);
            vh[base + 6] = __float2half_rn(o3);
        }
    }
}

extern "C" void kernel_launch(void* const* d_in, const int* in_sizes, int n_in,
                              void* d_out, int out_size) {
    const float* x = (const float*)d_in[0];
    const float* W = (const float*)d_in[1];
    if (n_in >= 2 && in_sizes[0] == C_DIM * U_DIM * D_DIM * I_DIM) {
        const float* t = x; x = W; W = t;
    }
    float* out = (float*)d_out;

    const int SM0 = 3 * 16384 + 3 * 2048;     // k_einsum ring-3
    const int SM1 = 3 * 65536;                // k_route ring-3 (192 KB)
    cudaFuncSetAttribute(k_einsum,   cudaFuncAttributeMaxDynamicSharedMemorySize, SM0);
    cudaFuncSetAttribute(k_route<1>, cudaFuncAttributeMaxDynamicSharedMemorySize, SM1);
    cudaFuncSetAttribute(k_route<2>, cudaFuncAttributeMaxDynamicSharedMemorySize, SM1);

    k_transpose<<<(C_DIM * B_DIM * I_DIM + 255) / 256, 256>>>(x);

    // iteration 1: einsum -> u_hat(fp16) + s1 -> v1
    k_einsum<<<NBLK, NTH, SM0>>>(W);
    k_redsquash<<<B_DIM, NTH>>>(out, 0);

    // iteration 2: stream u_hat: delta(v1), b = delta, softmax -> s2 -> v2
    k_route<1><<<NBLK, NTH, SM1>>>();
    k_redsquash<<<B_DIM, NTH>>>(out, 0);

    // iteration 3: stream u_hat: delta(v2), b += delta, softmax -> s3 -> v3
    k_route<2><<<NBLK, NTH, SM1>>>();
    k_redsquash<<<B_DIM, NTH>>>(out, 1);
}

// round 16
// speedup vs baseline: 1.0719x; 1.0719x over previous
#include <cuda_runtime.h>
#include <cuda_fp16.h>

#define C_DIM 2048
#define B_DIM 64
#define I_DIM 8
#define U_DIM 32
#define D_DIM 16
#define UD    512
#define NBLK  148
#define NTH   1024

typedef unsigned long long u64;
typedef unsigned int u32;

// ---- scratch (static __device__: allocation-free) ----
__device__ float g_xt[C_DIM * B_DIM * I_DIM];       // x transposed: [c][b][i]
__device__ float g_spart[NBLK * B_DIM * UD];        // per-block s partials
__device__ u32   g_vh[(B_DIM / 2) * UD];            // v half2 pairs: [b/2][ud]
__device__ float g_b[C_DIM * U_DIM];                // routing logits
__device__ u32   g_uh[C_DIM * (B_DIM / 2) * UD];    // u_hat half2: [c][b/2][ud] (128 MB)

__device__ __forceinline__ u64 mul2(u64 a, u64 b) {
    u64 r; asm("mul.rn.f32x2 %0, %1, %2;" : "=l"(r) : "l"(a), "l"(b)); return r;
}
__device__ __forceinline__ u64 fma2(u64 a, u64 b, u64 c) {
    u64 r; asm("fma.rn.f32x2 %0, %1, %2, %3;" : "=l"(r) : "l"(a), "l"(b), "l"(c)); return r;
}
__device__ __forceinline__ float hadd2(u64 a) {
    float lo, hi; asm("mov.b64 {%0,%1}, %2;" : "=f"(lo), "=f"(hi) : "l"(a));
    return lo + hi;
}
__device__ __forceinline__ u32 ldg_u32(const u32* p) {
    u32 r; asm volatile("ld.global.nc.b32 %0, [%1];" : "=r"(r) : "l"(p)); return r;
}
__device__ __forceinline__ u32 smem_u32(const void* p) {
    return (u32)__cvta_generic_to_shared(p);
}
__device__ __forceinline__ void lds_2u64(u32 a, u64& x, u64& y) {
    asm("ld.shared.v2.u64 {%0,%1}, [%2];" : "=l"(x), "=l"(y) : "r"(a));
}
__device__ __forceinline__ void lds_2u64v(u32 a, u64& x, u64& y) {
    asm volatile("ld.shared.v2.u64 {%0,%1}, [%2];" : "=l"(x), "=l"(y) : "r"(a));
}
__device__ __forceinline__ u32 lds_u32(u32 a) {
    u32 r; asm volatile("ld.shared.b32 %0, [%1];" : "=r"(r) : "r"(a)); return r;
}
__device__ __forceinline__ float dot8(u64 wa0, u64 wa1, u64 wb0, u64 wb1,
                                      u64 x0, u64 x1, u64 x2, u64 x3) {
    u64 acc = mul2(wa0, x0);
    acc = fma2(wa1, x1, acc);
    acc = fma2(wb0, x2, acc);
    acc = fma2(wb1, x3, acc);
    return hadd2(acc);
}

// ---- mbarrier + bulk-copy helpers ----
__device__ __forceinline__ void mbar_init(u32 a, u32 cnt) {
    asm volatile("mbarrier.init.shared.b64 [%0], %1;" :: "r"(a), "r"(cnt) : "memory");
}
__device__ __forceinline__ void fence_async() {
    asm volatile("fence.proxy.async.shared::cta;" ::: "memory");
}
__device__ __forceinline__ void mbar_expect(u32 a, u32 bytes) {
    asm volatile("mbarrier.arrive.expect_tx.shared.b64 _, [%0], %1;"
                 :: "r"(a), "r"(bytes) : "memory");
}
__device__ __forceinline__ void bulk_g2s(u32 dst, const void* src, u32 bytes, u32 mbar) {
    asm volatile("cp.async.bulk.shared::cta.global.mbarrier::complete_tx::bytes "
                 "[%0], [%1], %2, [%3];"
                 :: "r"(dst), "l"(src), "r"(bytes), "r"(mbar) : "memory");
}
__device__ __forceinline__ void mbar_wait(u32 a, u32 parity) {
    asm volatile(
        "{\n\t.reg .pred P;\n"
        "W_%=:\n\t"
        "mbarrier.try_wait.parity.shared.b64 P, [%0], %1;\n\t"
        "@!P bra W_%=;\n\t"
        "}" :: "r"(a), "r"(parity) : "memory");
}

// x (B,I,C) -> g_xt[c][b][i]
__global__ void k_transpose(const float* __restrict__ x) {
    int idx = blockIdx.x * blockDim.x + threadIdx.x;
    if (idx >= C_DIM * B_DIM * I_DIM) return;
    int c = idx >> 9;
    int r = idx & 511;
    int b = r >> 3;
    int i = r & 7;
    g_xt[idx] = x[(b * I_DIM + i) * C_DIM + c];
}

// ---------------------------------------------------------------------------
// p0: einsum -> u_hat (fp16, gmem) + s1 partials (uniform cij = 1/32).
// Ring-3 staged W/x via cp.async.bulk, copies issued 2 c ahead.
// Consumption safety comes from the ONE per-c __syncthreads: at the sync of
// iteration idx, all threads completed iteration idx-1, so stage (idx-1)%3
// (= the copy target (idx+2)%3) is free. No consumer barriers.
// ---------------------------------------------------------------------------
__global__ void __launch_bounds__(NTH, 1) k_einsum(const float* __restrict__ W) {
    extern __shared__ char dyn[];
    const u32 wbase = smem_u32(dyn);            // 3 x 16384 (W stages)
    const u32 xbase = wbase + 3 * 16384;        // 3 x 2048  (x stages)
    __shared__ u64 full_s[3];
    const u32 fb = smem_u32(full_s);

    const int tid  = threadIdx.x;
    const int w    = tid >> 5;
    const int lane = tid & 31;
    const int wu   = w & 15;
    const int wb   = w >> 4;
    const int ud   = wu * 32 + lane;

    float sacc[32];
#pragma unroll
    for (int r = 0; r < 32; r++) sacc[r] = 0.f;

    const int cbeg = (blockIdx.x * C_DIM) / NBLK;
    const int cend = ((blockIdx.x + 1) * C_DIM) / NBLK;
    const int n    = cend - cbeg;

    if (tid == 0) {
#pragma unroll
        for (int s = 0; s < 3; s++) mbar_init(fb + s * 8, 1);
        fence_async();
    }
    __syncthreads();
    if (tid == 0) {                  // prologue: stage c0 -> s0, c1 -> s1
#pragma unroll
        for (int j = 0; j < 2; j++) {
            mbar_expect(fb + j * 8, 18432);
            bulk_g2s(wbase + j * 16384, W + (size_t)(cbeg + j) * 4096, 16384, fb + j * 8);
            bulk_g2s(xbase + j * 2048, g_xt + (cbeg + j) * 512, 2048, fb + j * 8);
        }
    }

    int s = 0, fph = 0;
    for (int idx = 0; idx < n; idx++) {
        const int c = cbeg + idx;
        mbar_wait(fb + s * 8, fph);      // stage s holds c
        __syncthreads();                 // all threads completed iteration idx-1

        if (tid == 0 && idx + 2 < n) {   // stage c+2 into (idx+2)%3 = (idx-1)%3
            const int s2 = (s + 2 >= 3) ? s - 1 : s + 2;
            mbar_expect(fb + s2 * 8, 18432);
            bulk_g2s(wbase + s2 * 16384, W + (size_t)(c + 2) * 4096, 16384, fb + s2 * 8);
            bulk_g2s(xbase + s2 * 2048, g_xt + (c + 2) * 512, 2048, fb + s2 * 8);
        }

        u64 wa0, wa1, wbb0, wbb1;        // this lane's W row
        lds_2u64(wbase + s * 16384 + ud * 32, wa0, wa1);
        lds_2u64(wbase + s * 16384 + ud * 32 + 16, wbb0, wbb1);

        const u32 xb = xbase + s * 2048 + wb * 1024;
        u32* uout = g_uh + (size_t)c * 16384 + (wb * 16) * 512 + ud;

#pragma unroll
        for (int t = 0; t < 16; t++) {   // batch pair t -> b = wb*32+2t, +1
            u64 x0, x1, x2, x3, y0, y1, y2, y3;
            lds_2u64v(xb + t * 64,      x0, x1);
            lds_2u64v(xb + t * 64 + 16, x2, x3);
            lds_2u64v(xb + t * 64 + 32, y0, y1);
            lds_2u64v(xb + t * 64 + 48, y2, y3);
            float ua = dot8(wa0, wa1, wbb0, wbb1, x0, x1, x2, x3);
            float ub = dot8(wa0, wa1, wbb0, wbb1, y0, y1, y2, y3);
            sacc[2 * t]     += ua;
            sacc[2 * t + 1] += ub;
            __half2 h2 = __floats2half2_rn(ua, ub);
            uout[t * 512] = *(u32*)&h2;  // coalesced over lanes (ud)
        }

        if (++s == 3) { s = 0; fph ^= 1; }   // parity of stage s use-round
    }

    float* sp = g_spart + (size_t)blockIdx.x * (B_DIM * UD) + ud;
#pragma unroll
    for (int r = 0; r < 32; r++)
        sp[(wb * 32 + r) * UD] = sacc[r] * (1.0f / 32.0f);
}

// ---------------------------------------------------------------------------
// p1/p2: routing pass streaming u_hat. Ring-3 x 64KB, copies 2 c ahead.
// Phase A reads the tile into REGISTERS, so by the (single) per-c sync the
// stage is fully consumed -> tid0 issues the c+2 copy right after the sync.
// ---------------------------------------------------------------------------
template <int PASS>
__global__ void __launch_bounds__(NTH, 1) k_route() {
    extern __shared__ char dyn[];
    const u32 ubase = smem_u32(dyn);                // 3 x 65536
    __shared__ float red_sm[2][32];
    __shared__ u64 full_s[3];
    const u32 fb = smem_u32(full_s);

    const int tid  = threadIdx.x;
    const int w    = tid >> 5;
    const int lane = tid & 31;
    const int wu   = w & 15;
    const int wb   = w >> 4;
    const int hw   = lane >> 4;
    const int ud   = wu * 32 + lane;

    float sacc[32];
#pragma unroll
    for (int r = 0; r < 32; r++) sacc[r] = 0.f;

    const int cbeg = (blockIdx.x * C_DIM) / NBLK;
    const int cend = ((blockIdx.x + 1) * C_DIM) / NBLK;
    const int n    = cend - cbeg;

    if (tid == 0) {
#pragma unroll
        for (int s = 0; s < 3; s++) mbar_init(fb + s * 8, 1);
        fence_async();
    }
    __syncthreads();
    if (tid == 0) {                  // prologue: c0 -> s0, c1 -> s1
#pragma unroll
        for (int j = 0; j < 2; j++) {
            mbar_expect(fb + j * 8, 65536);
            bulk_g2s(ubase + j * 65536, g_uh + (size_t)(cbeg + j) * 16384, 65536, fb + j * 8);
        }
    }

    int s = 0, fph = 0;
    for (int idx = 0; idx < n; idx++) {
        const int c = cbeg + idx;
        mbar_wait(fb + s * 8, fph);                 // tile for c landed

        float bprev = (PASS == 2) ? g_b[c * U_DIM + lane] : 0.f;
        const u32 ub0 = ubase + s * 65536 + ((wb * 16) * 512 + ud) * 4;
        const u32* vb = g_vh + (wb * 16) * 512 + ud;
        float dp = 0.f;
        u32 pk[16];                                 // u_hat held in regs

#pragma unroll
        for (int t = 0; t < 16; t++) {
            pk[t] = lds_u32(ub0 + t * 2048);
            u32 vh = ldg_u32(vb + t * 512);
            float2 uu = __half22float2(*(__half2*)&pk[t]);
            float2 vv = __half22float2(*(__half2*)&vh);
            dp = fmaf(uu.x, vv.x, dp);
            dp = fmaf(uu.y, vv.y, dp);
        }

        // reduce dp over d (16-lane segments)
#pragma unroll
        for (int off = 8; off; off >>= 1)
            dp += __shfl_down_sync(0xffffffffu, dp, off, 16);
        if ((lane & 15) == 0)
            red_sm[wb][wu * 2 + hw] = dp;
        __syncthreads();        // red_sm ready AND all phase-A reads of stage s done

        if (tid == 0 && idx + 2 < n) {              // c+2 into (idx-1)%3 (free)
            const int s2 = (s + 2 >= 3) ? s - 1 : s + 2;
            mbar_expect(fb + s2 * 8, 65536);
            bulk_g2s(ubase + s2 * 65536, g_uh + (size_t)(c + 2) * 16384, 65536, fb + s2 * 8);
        }

        // redundant per-warp softmax over u (lane = u)
        float dv = red_sm[0][lane] + red_sm[1][lane];
        float bv = dv * (1.0f / 64.0f) + bprev;
        if (PASS == 1 && w == 0) g_b[c * U_DIM + lane] = bv;
        float m = bv;
#pragma unroll
        for (int off = 16; off; off >>= 1)
            m = fmaxf(m, __shfl_xor_sync(0xffffffffu, m, off));
        float e = __expf(bv - m);
        float ssum = e;
#pragma unroll
        for (int off = 16; off; off >>= 1)
            ssum += __shfl_xor_sync(0xffffffffu, ssum, off);
        float cij = __shfl_sync(0xffffffffu, e / ssum, wu * 2 + hw);

        // phase B: s += cij * u_hat (from registers)
#pragma unroll
        for (int t = 0; t < 16; t++) {
            float2 uu = __half22float2(*(__half2*)&pk[t]);
            sacc[2 * t]     = fmaf(cij, uu.x, sacc[2 * t]);
            sacc[2 * t + 1] = fmaf(cij, uu.y, sacc[2 * t + 1]);
        }
        if (++s == 3) { s = 0; fph ^= 1; }
    }

    float* sp = g_spart + (size_t)blockIdx.x * (B_DIM * UD) + ud;
#pragma unroll
    for (int r = 0; r < 32; r++)
        sp[(wb * 32 + r) * UD] = sacc[r];
}

// Reduce per-block s partials (float4, 8-way p-split), apply squash
// (mag over U axis — reference quirk). 1024 threads.
__global__ void k_redsquash(float* __restrict__ dout, int final_out) {
    __shared__ float4 part[8][128];
    __shared__ float sq[UD];
    __shared__ float rs[D_DIM];
    const int b   = blockIdx.x;
    const int tid = threadIdx.x;
    const int ph  = tid >> 7;
    const int j   = tid & 127;

    const float4* sp = ((const float4*)g_spart) + b * 128 + j;
    float4 a = make_float4(0.f, 0.f, 0.f, 0.f);
    for (int p = ph; p < NBLK; p += 8) {
        float4 t = sp[p * 8192];
        a.x += t.x; a.y += t.y; a.z += t.z; a.w += t.w;
    }
    part[ph][j] = a;
    __syncthreads();

    float4 s4 = make_float4(0.f, 0.f, 0.f, 0.f);
    if (ph == 0) {
#pragma unroll
        for (int q = 0; q < 8; q++) {
            float4 t = part[q][j];
            s4.x += t.x; s4.y += t.y; s4.z += t.z; s4.w += t.w;
        }
        sq[4 * j]     = s4.x * s4.x;
        sq[4 * j + 1] = s4.y * s4.y;
        sq[4 * j + 2] = s4.z * s4.z;
        sq[4 * j + 3] = s4.w * s4.w;
    }
    __syncthreads();
    if (tid < D_DIM) {
        float msq = 0.f;
#pragma unroll
        for (int u = 0; u < U_DIM; u++) msq += sq[u * D_DIM + tid];
        rs[tid] = sqrtf(msq) / (1.0f + msq);   // mag_sq/((1+mag_sq)*mag)
    }
    __syncthreads();
    if (ph == 0) {
        const int ud = 4 * j;
        float o0 = s4.x * rs[ud & 15];
        float o1 = s4.y * rs[(ud + 1) & 15];
        float o2 = s4.z * rs[(ud + 2) & 15];
        float o3 = s4.w * rs[(ud + 3) & 15];
        if (final_out) {
            ((float4*)dout)[b * 128 + j] = make_float4(o0, o1, o2, o3);
        } else {
            __half* vh = (__half*)g_vh;
            const int base = (b >> 1) * (UD * 2) + ud * 2 + (b & 1);
            vh[base]     = __float2half_rn(o0);
            vh[base + 2] = __float2half_rn(o1);
            vh[base + 4] = __float2half_rn(o2);
            vh[base + 6] = __float2half_rn(o3);
        }
    }
}

extern "C" void kernel_launch(void* const* d_in, const int* in_sizes, int n_in,
                              void* d_out, int out_size) {
    const float* x = (const float*)d_in[0];
    const float* W = (const float*)d_in[1];
    if (n_in >= 2 && in_sizes[0] == C_DIM * U_DIM * D_DIM * I_DIM) {
        const float* t = x; x = W; W = t;
    }
    float* out = (float*)d_out;

    const int SM0 = 3 * 16384 + 3 * 2048;     // k_einsum ring-3
    const int SM1 = 3 * 65536;                // k_route ring-3 (192 KB)
    cudaFuncSetAttribute(k_einsum,   cudaFuncAttributeMaxDynamicSharedMemorySize, SM0);
    cudaFuncSetAttribute(k_route<1>, cudaFuncAttributeMaxDynamicSharedMemorySize, SM1);
    cudaFuncSetAttribute(k_route<2>, cudaFuncAttributeMaxDynamicSharedMemorySize, SM1);

    k_transpose<<<(C_DIM * B_DIM * I_DIM + 255) / 256, 256>>>(x);

    // iteration 1: einsum -> u_hat(fp16) + s1 -> v1
    k_einsum<<<NBLK, NTH, SM0>>>(W);
    k_redsquash<<<B_DIM, NTH>>>(out, 0);

    // iteration 2: stream u_hat: delta(v1), b = delta, softmax -> s2 -> v2
    k_route<1><<<NBLK, NTH, SM1>>>();
    k_redsquash<<<B_DIM, NTH>>>(out, 0);

    // iteration 3: stream u_hat: delta(v2), b += delta, softmax -> s3 -> v3
    k_route<2><<<NBLK, NTH, SM1>>>();
    k_redsquash<<<B_DIM, NTH>>>(out, 1);
}

// round 17
// speedup vs baseline: 1.1287x; 1.0530x over previous
#include <cuda_runtime.h>
#include <cuda_fp16.h>

#define C_DIM 2048
#define B_DIM 64
#define I_DIM 8
#define U_DIM 32
#define D_DIM 16
#define UD    512
#define NBLK  148
#define NTH   1024

typedef unsigned long long u64;
typedef unsigned int u32;

// ---- scratch (static __device__: allocation-free) ----
__device__ float g_xt[C_DIM * B_DIM * I_DIM];       // x transposed: [c][b][i]
__device__ float g_spart[NBLK * B_DIM * UD];        // per-block s partials
__device__ u32   g_vh[(B_DIM / 2) * UD];            // v half2 pairs: [b/2][ud]
__device__ float g_b[C_DIM * U_DIM];                // routing logits
__device__ u32   g_uh[C_DIM * (B_DIM / 2) * UD];    // u_hat half2: [c][b/2][ud] (128 MB)

__device__ __forceinline__ u64 mul2(u64 a, u64 b) {
    u64 r; asm("mul.rn.f32x2 %0, %1, %2;" : "=l"(r) : "l"(a), "l"(b)); return r;
}
__device__ __forceinline__ u64 fma2(u64 a, u64 b, u64 c) {
    u64 r; asm("fma.rn.f32x2 %0, %1, %2, %3;" : "=l"(r) : "l"(a), "l"(b), "l"(c)); return r;
}
__device__ __forceinline__ float hadd2(u64 a) {
    float lo, hi; asm("mov.b64 {%0,%1}, %2;" : "=f"(lo), "=f"(hi) : "l"(a));
    return lo + hi;
}
__device__ __forceinline__ u32 ldg_u32(const u32* p) {
    u32 r; asm volatile("ld.global.nc.b32 %0, [%1];" : "=r"(r) : "l"(p)); return r;
}
__device__ __forceinline__ u32 smem_u32(const void* p) {
    return (u32)__cvta_generic_to_shared(p);
}
__device__ __forceinline__ void lds_2u64(u32 a, u64& x, u64& y) {
    asm("ld.shared.v2.u64 {%0,%1}, [%2];" : "=l"(x), "=l"(y) : "r"(a));
}
__device__ __forceinline__ void lds_2u64v(u32 a, u64& x, u64& y) {
    asm volatile("ld.shared.v2.u64 {%0,%1}, [%2];" : "=l"(x), "=l"(y) : "r"(a));
}
__device__ __forceinline__ u32 lds_u32(u32 a) {
    u32 r; asm volatile("ld.shared.b32 %0, [%1];" : "=r"(r) : "r"(a)); return r;
}
__device__ __forceinline__ void sts_u32(u32 a, u32 v) {
    asm volatile("st.shared.b32 [%0], %1;" :: "r"(a), "r"(v) : "memory");
}
__device__ __forceinline__ float dot8(u64 wa0, u64 wa1, u64 wb0, u64 wb1,
                                      u64 x0, u64 x1, u64 x2, u64 x3) {
    u64 acc = mul2(wa0, x0);
    acc = fma2(wa1, x1, acc);
    acc = fma2(wb0, x2, acc);
    acc = fma2(wb1, x3, acc);
    return hadd2(acc);
}

// ---- mbarrier + bulk-copy helpers ----
__device__ __forceinline__ void mbar_init(u32 a, u32 cnt) {
    asm volatile("mbarrier.init.shared.b64 [%0], %1;" :: "r"(a), "r"(cnt) : "memory");
}
__device__ __forceinline__ void fence_async() {
    asm volatile("fence.proxy.async.shared::cta;" ::: "memory");
}
__device__ __forceinline__ void mbar_expect(u32 a, u32 bytes) {
    asm volatile("mbarrier.arrive.expect_tx.shared.b64 _, [%0], %1;"
                 :: "r"(a), "r"(bytes) : "memory");
}
__device__ __forceinline__ void bulk_g2s(u32 dst, const void* src, u32 bytes, u32 mbar) {
    asm volatile("cp.async.bulk.shared::cta.global.mbarrier::complete_tx::bytes "
                 "[%0], [%1], %2, [%3];"
                 :: "r"(dst), "l"(src), "r"(bytes), "r"(mbar) : "memory");
}
__device__ __forceinline__ void bulk_s2g(void* gdst, u32 ssrc, u32 bytes) {
    asm volatile("cp.async.bulk.global.shared::cta.bulk_group [%0], [%1], %2;"
                 :: "l"(gdst), "r"(ssrc), "r"(bytes) : "memory");
}
#define BULK_COMMIT() asm volatile("cp.async.bulk.commit_group;" ::: "memory")
#define BULK_WAIT(N)  asm volatile("cp.async.bulk.wait_group %0;" :: "n"(N) : "memory")
__device__ __forceinline__ void mbar_wait(u32 a, u32 parity) {
    asm volatile(
        "{\n\t.reg .pred P;\n"
        "W_%=:\n\t"
        "mbarrier.try_wait.parity.shared.b64 P, [%0], %1;\n\t"
        "@!P bra W_%=;\n\t"
        "}" :: "r"(a), "r"(parity) : "memory");
}

// x (B,I,C) -> g_xt[c][b][i]
__global__ void k_transpose(const float* __restrict__ x) {
    int idx = blockIdx.x * blockDim.x + threadIdx.x;
    if (idx >= C_DIM * B_DIM * I_DIM) return;
    int c = idx >> 9;
    int r = idx & 511;
    int b = r >> 3;
    int i = r & 7;
    g_xt[idx] = x[(b * I_DIM + i) * C_DIM + c];
}

// ---------------------------------------------------------------------------
// p0: einsum -> u_hat (fp16) + s1 partials. W/x staged depth-2 via bulk G2S
// (R14 scheme). u_hat written via STS into a ring-2 smem tile, flushed to
// gmem with ONE cp.async.bulk S2G per c (TMA does the 128 MB write stream).
// ---------------------------------------------------------------------------
__global__ void __launch_bounds__(NTH, 1) k_einsum(const float* __restrict__ W) {
    extern __shared__ char dyn[];
    const u32 wbase = smem_u32(dyn);            // Wbuf[2][16384]
    const u32 xbase = wbase + 32768;            // xbuf[2][2048]
    const u32 obase = xbase + 4096;             // outbuf[2][65536]
    __shared__ u64 mbar_s;
    const u32 mb = smem_u32(&mbar_s);

    const int tid  = threadIdx.x;
    const int w    = tid >> 5;
    const int lane = tid & 31;
    const int wu   = w & 15;
    const int wb   = w >> 4;
    const int ud   = wu * 32 + lane;

    float sacc[32];
#pragma unroll
    for (int r = 0; r < 32; r++) sacc[r] = 0.f;

    const int cbeg = (blockIdx.x * C_DIM) / NBLK;
    const int cend = ((blockIdx.x + 1) * C_DIM) / NBLK;
    const int n    = cend - cbeg;

    if (tid == 0) { mbar_init(mb, 1); fence_async(); }
    __syncthreads();
    if (tid == 0) {
        mbar_expect(mb, 18432);
        bulk_g2s(wbase, W + (size_t)cbeg * 4096, 16384, mb);
        bulk_g2s(xbase, g_xt + cbeg * 512, 2048, mb);
    }

    for (int idx = 0; idx < n; idx++) {
        const int c   = cbeg + idx;
        const int par = idx & 1;
        mbar_wait(mb, par);              // W/x for c landed in buf[par]
        __syncthreads();                 // sync1: all STS of c-1 complete

        if (tid == 0) {
            if (idx > 0) {               // flush c-1's tile; ensure c-2 flushed
                fence_async();
                bulk_s2g(g_uh + (size_t)(c - 1) * 16384, obase + (par ^ 1) * 65536, 65536);
                BULK_COMMIT();
                BULK_WAIT(1);            // S2G(c-2) done -> outbuf[par] free
            }
            if (idx + 1 < n) {           // stage W/x for c+1
                mbar_expect(mb, 18432);
                bulk_g2s(wbase + (par ^ 1) * 16384, W + (size_t)(c + 1) * 4096, 16384, mb);
                bulk_g2s(xbase + (par ^ 1) * 2048, g_xt + (c + 1) * 512, 2048, mb);
            }
        }
        __syncthreads();                 // sync2: outbuf[par] free for writing

        u64 wa0, wa1, wbb0, wbb1;        // this lane's W row
        lds_2u64(wbase + par * 16384 + ud * 32, wa0, wa1);
        lds_2u64(wbase + par * 16384 + ud * 32 + 16, wbb0, wbb1);

        const u32 xb = xbase + par * 2048 + wb * 1024;
        const u32 ob = obase + par * 65536 + ((wb * 16) * 512 + ud) * 4;

#pragma unroll
        for (int t = 0; t < 16; t++) {   // batch pair t -> b = wb*32+2t, +1
            u64 x0, x1, x2, x3, y0, y1, y2, y3;
            lds_2u64v(xb + t * 64,      x0, x1);
            lds_2u64v(xb + t * 64 + 16, x2, x3);
            lds_2u64v(xb + t * 64 + 32, y0, y1);
            lds_2u64v(xb + t * 64 + 48, y2, y3);
            float ua = dot8(wa0, wa1, wbb0, wbb1, x0, x1, x2, x3);
            float ub = dot8(wa0, wa1, wbb0, wbb1, y0, y1, y2, y3);
            sacc[2 * t]     += ua;
            sacc[2 * t + 1] += ub;
            __half2 h2 = __floats2half2_rn(ua, ub);
            sts_u32(ob + t * 2048, *(u32*)&h2);   // bank-perfect STS
        }
    }

    __syncthreads();                     // last tile fully written
    if (tid == 0) {                      // flush final tile
        fence_async();
        bulk_s2g(g_uh + (size_t)(cend - 1) * 16384, obase + ((n - 1) & 1) * 65536, 65536);
        BULK_COMMIT();
        BULK_WAIT(0);
    }

    float* sp = g_spart + (size_t)blockIdx.x * (B_DIM * UD) + ud;
#pragma unroll
    for (int r = 0; r < 32; r++)
        sp[(wb * 32 + r) * UD] = sacc[r] * (1.0f / 32.0f);
}

// ---------------------------------------------------------------------------
// p1/p2: routing pass streaming u_hat. R14 depth-2 pipeline (copy issued
// right after the top sync), u_hat held in registers for phase B.
// ---------------------------------------------------------------------------
template <int PASS>
__global__ void __launch_bounds__(NTH, 1) k_route() {
    extern __shared__ char dyn[];
    const u32 ubase = smem_u32(dyn);                // ubuf[2][65536]
    __shared__ float red_sm[2][32];
    __shared__ u64 mbar_s;
    const u32 mb = smem_u32(&mbar_s);

    const int tid  = threadIdx.x;
    const int w    = tid >> 5;
    const int lane = tid & 31;
    const int wu   = w & 15;
    const int wb   = w >> 4;
    const int hw   = lane >> 4;
    const int ud   = wu * 32 + lane;

    float sacc[32];
#pragma unroll
    for (int r = 0; r < 32; r++) sacc[r] = 0.f;

    const int cbeg = (blockIdx.x * C_DIM) / NBLK;
    const int cend = ((blockIdx.x + 1) * C_DIM) / NBLK;
    const int n    = cend - cbeg;

    if (tid == 0) { mbar_init(mb, 1); fence_async(); }
    __syncthreads();
    if (tid == 0) {
        mbar_expect(mb, 65536);
        bulk_g2s(ubase, g_uh + (size_t)cbeg * 16384, 65536, mb);
    }

    for (int idx = 0; idx < n; idx++) {
        const int c   = cbeg + idx;
        const int par = idx & 1;
        mbar_wait(mb, par);              // tile for c landed in buf[par]
        __syncthreads();                 // all phase-A reads of buf[par^1] done
        if (tid == 0 && idx + 1 < n) {   // issue EARLY: overlaps all compute
            mbar_expect(mb, 65536);
            bulk_g2s(ubase + (par ^ 1) * 65536,
                     g_uh + (size_t)(c + 1) * 16384, 65536, mb);
        }

        float bprev = (PASS == 2) ? g_b[c * U_DIM + lane] : 0.f;
        const u32 ub0 = ubase + par * 65536 + ((wb * 16) * 512 + ud) * 4;
        const u32* vb = g_vh + (wb * 16) * 512 + ud;
        float dp = 0.f;
        u32 pk[16];                      // u_hat held in regs for phase B

#pragma unroll
        for (int t = 0; t < 16; t++) {
            pk[t] = lds_u32(ub0 + t * 2048);
            u32 vh = ldg_u32(vb + t * 512);
            float2 uu = __half22float2(*(__half2*)&pk[t]);
            float2 vv = __half22float2(*(__half2*)&vh);
            dp = fmaf(uu.x, vv.x, dp);
            dp = fmaf(uu.y, vv.y, dp);
        }

        // reduce dp over d (16-lane segments)
#pragma unroll
        for (int off = 8; off; off >>= 1)
            dp += __shfl_down_sync(0xffffffffu, dp, off, 16);
        if ((lane & 15) == 0)
            red_sm[wb][wu * 2 + hw] = dp;
        __syncthreads();                 // red_sm ready

        // redundant per-warp softmax over u (lane = u)
        float dv = red_sm[0][lane] + red_sm[1][lane];
        float bv = dv * (1.0f / 64.0f) + bprev;
        if (PASS == 1 && w == 0) g_b[c * U_DIM + lane] = bv;
        float m = bv;
#pragma unroll
        for (int off = 16; off; off >>= 1)
            m = fmaxf(m, __shfl_xor_sync(0xffffffffu, m, off));
        float e = __expf(bv - m);
        float ssum = e;
#pragma unroll
        for (int off = 16; off; off >>= 1)
            ssum += __shfl_xor_sync(0xffffffffu, ssum, off);
        float cij = __shfl_sync(0xffffffffu, e / ssum, wu * 2 + hw);

        // phase B: s += cij * u_hat (from registers)
#pragma unroll
        for (int t = 0; t < 16; t++) {
            float2 uu = __half22float2(*(__half2*)&pk[t]);
            sacc[2 * t]     = fmaf(cij, uu.x, sacc[2 * t]);
            sacc[2 * t + 1] = fmaf(cij, uu.y, sacc[2 * t + 1]);
        }
    }

    float* sp = g_spart + (size_t)blockIdx.x * (B_DIM * UD) + ud;
#pragma unroll
    for (int r = 0; r < 32; r++)
        sp[(wb * 32 + r) * UD] = sacc[r];
}

// Reduce per-block s partials (float4, 8-way p-split), apply squash
// (mag over U axis — reference quirk). 1024 threads.
__global__ void k_redsquash(float* __restrict__ dout, int final_out) {
    __shared__ float4 part[8][128];
    __shared__ float sq[UD];
    __shared__ float rs[D_DIM];
    const int b   = blockIdx.x;
    const int tid = threadIdx.x;
    const int ph  = tid >> 7;
    const int j   = tid & 127;

    const float4* sp = ((const float4*)g_spart) + b * 128 + j;
    float4 a = make_float4(0.f, 0.f, 0.f, 0.f);
    for (int p = ph; p < NBLK; p += 8) {
        float4 t = sp[p * 8192];
        a.x += t.x; a.y += t.y; a.z += t.z; a.w += t.w;
    }
    part[ph][j] = a;
    __syncthreads();

    float4 s4 = make_float4(0.f, 0.f, 0.f, 0.f);
    if (ph == 0) {
#pragma unroll
        for (int q = 0; q < 8; q++) {
            float4 t = part[q][j];
            s4.x += t.x; s4.y += t.y; s4.z += t.z; s4.w += t.w;
        }
        sq[4 * j]     = s4.x * s4.x;
        sq[4 * j + 1] = s4.y * s4.y;
        sq[4 * j + 2] = s4.z * s4.z;
        sq[4 * j + 3] = s4.w * s4.w;
    }
    __syncthreads();
    if (tid < D_DIM) {
        float msq = 0.f;
#pragma unroll
        for (int u = 0; u < U_DIM; u++) msq += sq[u * D_DIM + tid];
        rs[tid] = sqrtf(msq) / (1.0f + msq);   // mag_sq/((1+mag_sq)*mag)
    }
    __syncthreads();
    if (ph == 0) {
        const int ud = 4 * j;
        float o0 = s4.x * rs[ud & 15];
        float o1 = s4.y * rs[(ud + 1) & 15];
        float o2 = s4.z * rs[(ud + 2) & 15];
        float o3 = s4.w * rs[(ud + 3) & 15];
        if (final_out) {
            ((float4*)dout)[b * 128 + j] = make_float4(o0, o1, o2, o3);
        } else {
            __half* vh = (__half*)g_vh;
            const int base = (b >> 1) * (UD * 2) + ud * 2 + (b & 1);
            vh[base]     = __float2half_rn(o0);
            vh[base + 2] = __float2half_rn(o1);
            vh[base + 4] = __float2half_rn(o2);
            vh[base + 6] = __float2half_rn(o3);
        }
    }
}

extern "C" void kernel_launch(void* const* d_in, const int* in_sizes, int n_in,
                              void* d_out, int out_size) {
    const float* x = (const float*)d_in[0];
    const float* W = (const float*)d_in[1];
    if (n_in >= 2 && in_sizes[0] == C_DIM * U_DIM * D_DIM * I_DIM) {
        const float* t = x; x = W; W = t;
    }
    float* out = (float*)d_out;

    const int SM0 = 32768 + 4096 + 2 * 65536;  // W/x depth-2 + out ring-2 (164 KB)
    const int SM1 = 2 * 65536;                 // route depth-2 (128 KB)
    cudaFuncSetAttribute(k_einsum,   cudaFuncAttributeMaxDynamicSharedMemorySize, SM0);
    cudaFuncSetAttribute(k_route<1>, cudaFuncAttributeMaxDynamicSharedMemorySize, SM1);
    cudaFuncSetAttribute(k_route<2>, cudaFuncAttributeMaxDynamicSharedMemorySize, SM1);

    k_transpose<<<(C_DIM * B_DIM * I_DIM + 255) / 256, 256>>>(x);

    // iteration 1: einsum -> u_hat(fp16) + s1 -> v1
    k_einsum<<<NBLK, NTH, SM0>>>(W);
    k_redsquash<<<B_DIM, NTH>>>(out, 0);

    // iteration 2: stream u_hat: delta(v1), b = delta, softmax -> s2 -> v2
    k_route<1><<<NBLK, NTH, SM1>>>();
    k_redsquash<<<B_DIM, NTH>>>(out, 0);

    // iteration 3: stream u_hat: delta(v2), b += delta, softmax -> s3 -> v3
    k_route<2><<<NBLK, NTH, SM1>>>();
    k_redsquash<<<B_DIM, NTH>>>(out, 1);
}